// round 1
// baseline (speedup 1.0000x reference)
#include <cuda_runtime.h>

#define BB 8
#define CC 64
#define NN 4096
#define KK 16
#define EE 64
#define NPOINTS (BB*NN)            // 32768
#define CNT1 524288.0f             // B*N*K
#define CNT3 32768.0f              // B*N
#define EPSV 1e-5f

// Scratch (device globals: allocation-free rule)
__device__ float g_y1t[NPOINTS*EE];       // 8 MB   y1 transposed: [b*N+n][e]
__device__ float g_z2[NPOINTS*KK*EE];     // 134 MB pre-BN layer-2 output: [point][k][o]
__device__ float g_sum1[EE], g_sumsq1[EE];
__device__ float g_sum2[EE], g_sumsq2[EE];
__device__ float g_sum3[EE], g_sumsq3[EE];
__device__ float g_a1[EE], g_c1[EE];
__device__ float g_a2[EE], g_c2[EE];
__device__ float g_a3[EE], g_c3[EE];

__global__ void k_zero() {
    int t = threadIdx.x;
    if (t < EE) {
        g_sum1[t]=0.f; g_sumsq1[t]=0.f;
        g_sum2[t]=0.f; g_sumsq2[t]=0.f;
        g_sum3[t]=0.f; g_sumsq3[t]=0.f;
    }
}

// y1t[b][n][e] = sum_c W1[e][c] * x[b][c][n]
__global__ void k_y1(const float* __restrict__ x, const float* __restrict__ W1) {
    __shared__ float xs[CC][64];
    __shared__ float W1sT[CC][EE];
    int b = blockIdx.y;
    int n0 = blockIdx.x * 64;
    int t = threadIdx.x;
    for (int i = t; i < CC*EE; i += 256) {
        int o = i >> 6, c = i & 63;
        W1sT[c][o] = W1[i];
    }
    for (int i = t; i < CC*64; i += 256) {
        int c = i >> 6, j = i & 63;
        xs[c][j] = x[(b*CC + c)*NN + n0 + j];
    }
    __syncthreads();
    int e = t & 63;
    int nb = (t >> 6) * 16;
    float acc[16];
    #pragma unroll
    for (int i = 0; i < 16; i++) acc[i] = 0.f;
    #pragma unroll 4
    for (int c = 0; c < CC; c++) {
        float w = W1sT[c][e];
        #pragma unroll
        for (int i = 0; i < 16; i++) acc[i] = fmaf(w, xs[c][nb+i], acc[i]);
    }
    #pragma unroll
    for (int i = 0; i < 16; i++)
        g_y1t[(b*NN + n0 + nb + i)*EE + e] = acc[i];
}

// BN1 stats: per-channel sum / sumsq of d = y1t[j] - y1t[n] over all (b,n,k)
__global__ void k_stats1(const int* __restrict__ idx) {
    __shared__ float red[4][64];
    int t = threadIdx.x;
    int c = t & 63, g = t >> 6;
    float s = 0.f, q = 0.f;
    int p0 = blockIdx.x * 64;
    for (int pl = g; pl < 64; pl += 4) {
        int point = p0 + pl;
        int brow = (point >> 12) << 12;
        float yn = g_y1t[point*EE + c];
        const int* ip = idx + point*KK;
        #pragma unroll
        for (int k = 0; k < KK; k++) {
            int j = ip[k];
            float yj = g_y1t[(brow + j)*EE + c];
            float d = yj - yn;
            s += d;
            q = fmaf(d, d, q);
        }
    }
    red[g][c] = s;
    __syncthreads();
    if (g == 0) atomicAdd(&g_sum1[c], red[0][c]+red[1][c]+red[2][c]+red[3][c]);
    __syncthreads();
    red[g][c] = q;
    __syncthreads();
    if (g == 0) atomicAdd(&g_sumsq1[c], red[0][c]+red[1][c]+red[2][c]+red[3][c]);
}

// Fold BN stats into per-channel affine a,c (bias cancels inside BN)
__global__ void k_fin(int layer, float cnt,
                      const float* __restrict__ gam, const float* __restrict__ bet) {
    int e = threadIdx.x;
    if (e >= EE) return;
    const float* sum; const float* sq; float* a; float* cv;
    if (layer == 1)      { sum=g_sum1; sq=g_sumsq1; a=g_a1; cv=g_c1; }
    else if (layer == 2) { sum=g_sum2; sq=g_sumsq2; a=g_a2; cv=g_c2; }
    else                 { sum=g_sum3; sq=g_sumsq3; a=g_a3; cv=g_c3; }
    float m = sum[e] / cnt;
    float v = sq[e] / cnt - m*m;
    v = fmaxf(v, 0.f);
    float av = gam[e] * rsqrtf(v + EPSV);
    a[e] = av;
    cv[e] = bet[e] - av * m;
}

// Main pass: h1 = relu(a1*(y_j - y_n)+c1); z2 = W2@h1 -> scratch; accumulate BN2 stats
__global__ void __launch_bounds__(64) k_main1(const int* __restrict__ idx,
                                              const float* __restrict__ W2) {
    __shared__ __align__(16) float h1s[KK][EE];
    int t = threadIdx.x;
    float4 w4[16];
    const float4* W2v = (const float4*)(W2 + t*CC);
    #pragma unroll
    for (int qq = 0; qq < 16; qq++) w4[qq] = W2v[qq];
    float a1t = g_a1[t], c1t = g_c1[t];
    float sz = 0.f, szq = 0.f;
    int p0 = blockIdx.x * 16;
    for (int p = 0; p < 16; p++) {
        int point = p0 + p;
        int brow = (point >> 12) << 12;
        float yn = g_y1t[point*EE + t];
        const int* ip = idx + point*KK;
        #pragma unroll
        for (int k = 0; k < KK; k++) {
            int j = ip[k];
            float yj = g_y1t[(brow + j)*EE + t];
            h1s[k][t] = fmaxf(fmaf(a1t, yj - yn, c1t), 0.f);
        }
        __syncthreads();
        #pragma unroll 4
        for (int k = 0; k < KK; k++) {
            const float4* h4 = (const float4*)(&h1s[k][0]);
            float z0=0.f, z1=0.f, z2v=0.f, z3=0.f;
            #pragma unroll
            for (int qq = 0; qq < 16; qq++) {
                float4 hv = h4[qq];
                z0  = fmaf(w4[qq].x, hv.x, z0);
                z1  = fmaf(w4[qq].y, hv.y, z1);
                z2v = fmaf(w4[qq].z, hv.z, z2v);
                z3  = fmaf(w4[qq].w, hv.w, z3);
            }
            float z = (z0+z1)+(z2v+z3);
            g_z2[(point*KK + k)*EE + t] = z;
            sz += z;
            szq = fmaf(z, z, szq);
        }
        __syncthreads();
    }
    atomicAdd(&g_sum2[t], sz);
    atomicAdd(&g_sumsq2[t], szq);
}

// max over k of relu(a2*z2+c2), then z3 = W3@m written straight into out (B,E,N)
__global__ void k_pool3(const float* __restrict__ W3, float* __restrict__ out) {
    __shared__ float ms[64][65];
    __shared__ float W3sT[CC][EE];
    int b = blockIdx.y;
    int n0 = blockIdx.x * 64;
    int t = threadIdx.x;
    for (int i = t; i < CC*EE; i += 256) {
        int o = i >> 6, c = i & 63;
        W3sT[c][o] = W3[i];
    }
    {
        int o = t & 63;
        int ng = t >> 6;
        float a2o = g_a2[o], c2o = g_c2[o];
        for (int nl = ng; nl < 64; nl += 4) {
            int point = b*NN + n0 + nl;
            const float* zp = g_z2 + (size_t)point*KK*EE + o;
            float m = 0.f;   // relu output >= 0, so 0 is a valid identity for max
            #pragma unroll
            for (int k = 0; k < KK; k++) {
                float v = zp[k*EE];
                m = fmaxf(m, fmaxf(fmaf(a2o, v, c2o), 0.f));
            }
            ms[nl][o] = m;
        }
    }
    __syncthreads();
    int nl = t & 63;
    int ob = (t >> 6) * 16;
    float acc[16];
    #pragma unroll
    for (int i = 0; i < 16; i++) acc[i] = 0.f;
    #pragma unroll 4
    for (int c = 0; c < CC; c++) {
        float mv = ms[nl][c];
        #pragma unroll
        for (int i = 0; i < 16; i++)
            acc[i] = fmaf(W3sT[c][ob+i], mv, acc[i]);
    }
    #pragma unroll
    for (int i = 0; i < 16; i++)
        out[(b*EE + ob + i)*NN + n0 + nl] = acc[i];
}

// BN3 stats: one CTA per (b,o) plane of out (holds pre-BN z3)
__global__ void k_stats3(const float* __restrict__ out) {
    __shared__ float r1[256], r2[256];
    int p = blockIdx.x;        // p = b*64 + o
    int o = p & 63;
    const float* base = out + (size_t)p*NN;
    int t = threadIdx.x;
    float s = 0.f, q = 0.f;
    for (int i = t; i < NN; i += 256) {
        float v = base[i];
        s += v;
        q = fmaf(v, v, q);
    }
    r1[t] = s; r2[t] = q;
    __syncthreads();
    for (int w = 128; w > 0; w >>= 1) {
        if (t < w) { r1[t] += r1[t+w]; r2[t] += r2[t+w]; }
        __syncthreads();
    }
    if (t == 0) {
        atomicAdd(&g_sum3[o], r1[0]);
        atomicAdd(&g_sumsq3[o], r2[0]);
    }
}

// In-place BN3 + ReLU
__global__ void k_out(float* __restrict__ out) {
    int i = blockIdx.x * blockDim.x + threadIdx.x;
    int o = (i >> 12) & 63;
    out[i] = fmaxf(fmaf(g_a3[o], out[i], g_c3[o]), 0.f);
}

extern "C" void kernel_launch(void* const* d_in, const int* in_sizes, int n_in,
                              void* d_out, int out_size) {
    const float* x   = (const float*)d_in[0];
    const int*   idx = (const int*)  d_in[1];
    const float* W1  = (const float*)d_in[2];
    const float* g1  = (const float*)d_in[4];
    const float* be1 = (const float*)d_in[5];
    const float* W2  = (const float*)d_in[6];
    const float* g2  = (const float*)d_in[8];
    const float* be2 = (const float*)d_in[9];
    const float* W3  = (const float*)d_in[10];
    const float* g3  = (const float*)d_in[12];
    const float* be3 = (const float*)d_in[13];
    float* out = (float*)d_out;

    k_zero  <<<1, 64>>>();
    k_y1    <<<dim3(64, 8), 256>>>(x, W1);
    k_stats1<<<512, 256>>>(idx);
    k_fin   <<<1, 64>>>(1, CNT1, g1, be1);
    k_main1 <<<2048, 64>>>(idx, W2);
    k_fin   <<<1, 64>>>(2, CNT1, g2, be2);
    k_pool3 <<<dim3(64, 8), 256>>>(W3, out);
    k_stats3<<<512, 256>>>(out);
    k_fin   <<<1, 64>>>(3, CNT3, g3, be3);
    k_out   <<<8192, 256>>>(out);
}